// round 15
// baseline (speedup 1.0000x reference)
#include <cuda_runtime.h>
#include <cuda_fp16.h>
#include <math.h>
#include <stdint.h>

#define N_SRC   10000
#define N_DST   10000
#define N_TOT   20000
#define IN_SRC  512
#define IN_DST  256
#define HID     512
#define OUTD    256
#define N_EDGES 160000
#define EPS     1e-5f
#define MREG    10000
#define YTILES  79

// ---------------- device scratch (fp16 hi/lo activations, fp16 single weights) --------
__device__ __align__(16) __half g_AH[(size_t)N_TOT * HID];
__device__ __align__(16) __half g_AL[(size_t)N_TOT * HID];
__device__ __align__(16) __half g_X1H[(size_t)N_TOT * HID];
__device__ __align__(16) __half g_X1L[(size_t)N_TOT * HID];
__device__ __align__(16) __half g_MH[(size_t)N_DST * HID];
__device__ __align__(16) __half g_ML[(size_t)N_DST * HID];
__device__ __align__(16) __half g_XSH[(size_t)N_SRC * IN_SRC], g_XSL[(size_t)N_SRC * IN_SRC];
__device__ __align__(16) __half g_XDH[(size_t)N_DST * IN_DST], g_XDL[(size_t)N_DST * IN_DST];
__device__ __align__(16) __half g_WS[HID * IN_SRC];
__device__ __align__(16) __half g_WD[HID * IN_DST];
__device__ __align__(16) __half g_W1L[HID * HID];
__device__ __align__(16) __half g_W1R[HID * HID];
__device__ __align__(16) __half g_W2L[OUTD * HID];
__device__ __align__(16) __half g_W2R[OUTD * HID];
__device__ int   g_SRC[N_EDGES];
__device__ int   g_DSTL[N_EDGES];
__device__ int   g_IS64;
__device__ int   g_CNT[N_DST];
__device__ int   g_ROWPTR[N_DST + 1];
__device__ int   g_CURSOR[N_DST];
__device__ int   g_ESRC[N_EDGES];
__device__ float g_SUM[HID];
__device__ float g_SSQ[HID];
__device__ int   g_TQ[4];

// ---------------- helpers ----------------
__device__ __forceinline__ uint32_t smem_u32(const void* p) {
    uint32_t a;
    asm("{ .reg .u64 t; cvta.to.shared.u64 t, %1; cvt.u32.u64 %0, t; }" : "=r"(a) : "l"(p));
    return a;
}
__device__ __forceinline__ void cpa(uint32_t d, const void* s, int sz) {
    asm volatile("cp.async.cg.shared.global [%0], [%1], 16, %2;"
                 :: "r"(d), "l"(s), "r"(sz) : "memory");
}
__device__ __forceinline__ void ldm_x4(uint32_t* r, uint32_t a) {
    asm volatile("ldmatrix.sync.aligned.m8n8.x4.shared.b16 {%0,%1,%2,%3}, [%4];"
                 : "=r"(r[0]), "=r"(r[1]), "=r"(r[2]), "=r"(r[3]) : "r"(a));
}
__device__ __forceinline__ void mma_f16(float* d, const uint32_t* a, const uint32_t* b) {
    asm("mma.sync.aligned.m16n8k16.row.col.f32.f16.f16.f32 "
        "{%0,%1,%2,%3}, {%4,%5,%6,%7}, {%8,%9}, {%0,%1,%2,%3};"
        : "+f"(d[0]), "+f"(d[1]), "+f"(d[2]), "+f"(d[3])
        : "r"(a[0]), "r"(a[1]), "r"(a[2]), "r"(a[3]), "r"(b[0]), "r"(b[1]));
}
__device__ __forceinline__ void split_hl(float v, __half& h, __half& l) {
    h = __float2half_rn(v);
    l = __float2half_rn(v - __half2float(h));
}

// ---------------- init: zero counts + queues + BN accum + dtype detect ---------------
__global__ void k_init(const int* __restrict__ ei32) {
    int i = blockIdx.x * blockDim.x + threadIdx.x;
    if (i < N_DST) g_CNT[i] = 0;
    if (i < 4) g_TQ[i] = 0;
    if (i < HID) { g_SUM[i] = 0.f; g_SSQ[i] = 0.f; }
    if (blockIdx.x == 0 && threadIdx.x == 0) {
        int allzero = 1;
        for (int j = 0; j < 64; j++)
            if (ei32[2 * j + 1] != 0) { allzero = 0; break; }
        g_IS64 = allzero;
    }
}
// fused decode + histogram
__global__ void k_decode_count(const void* __restrict__ ei) {
    int e = blockIdx.x * blockDim.x + threadIdx.x;
    if (e >= N_EDGES) return;
    int s, d;
    if (g_IS64) {
        const long long* p = (const long long*)ei;
        s = (int)p[e]; d = (int)p[N_EDGES + e];
    } else {
        const int* p = (const int*)ei;
        s = p[e]; d = p[N_EDGES + e];
    }
    int dl = d - N_SRC;
    g_SRC[e] = s;
    g_DSTL[e] = dl;
    if (dl >= 0 && dl < N_DST) atomicAdd(&g_CNT[dl], 1);
}
__global__ void k_scan() {
    __shared__ int s[1024];
    const int t = threadIdx.x;
    const int base = t * 10;
    int vals[10];
    int local = 0;
#pragma unroll
    for (int i = 0; i < 10; i++) {
        int idx = base + i;
        int v = (idx < N_DST) ? g_CNT[idx] : 0;
        vals[i] = v; local += v;
    }
    s[t] = local;
    __syncthreads();
    for (int off = 1; off < 1024; off <<= 1) {
        int v = (t >= off) ? s[t - off] : 0;
        __syncthreads();
        s[t] += v;
        __syncthreads();
    }
    int run = (t == 0) ? 0 : s[t - 1];
#pragma unroll
    for (int i = 0; i < 10; i++) {
        int idx = base + i;
        if (idx < N_DST) { g_ROWPTR[idx] = run; g_CURSOR[idx] = run; run += vals[i]; }
    }
    if (t == 1023) g_ROWPTR[N_DST] = s[1023];
}
__global__ void k_fill() {
    int e = blockIdx.x * blockDim.x + threadIdx.x;
    if (e < N_EDGES) {
        int d = g_DSTL[e];
        int s = g_SRC[e];
        if (d >= 0 && d < N_DST && s >= 0 && s < N_TOT) {
            int pos = atomicAdd(&g_CURSOR[d], 1);
            if (pos < N_EDGES) g_ESRC[pos] = s;
        }
    }
}

// ---------------- batched fp32 -> fp16 conversion (split when l != null) -------------
struct ConvTab {
    const float* s[8];
    __half* h[8];
    __half* l[8];
    int end[8];
};
__global__ void k_conv_all(ConvTab tb) {
    int i = blockIdx.x * blockDim.x + threadIdx.x;
    if (i >= tb.end[7]) return;
    int sg = 0;
#pragma unroll
    for (int j = 0; j < 7; j++) sg += (i >= tb.end[j]);
    int base = sg ? tb.end[sg - 1] : 0;
    int off = i - base;
    float4 v = ((const float4*)tb.s[sg])[off];
    if (tb.l[sg]) {
        __half hx, hy, hz, hw, lx, ly, lz, lw;
        split_hl(v.x, hx, lx); split_hl(v.y, hy, ly);
        split_hl(v.z, hz, lz); split_hl(v.w, hw, lw);
        ((__half2*)tb.h[sg])[2 * off] = __halves2half2(hx, hy);
        ((__half2*)tb.h[sg])[2 * off + 1] = __halves2half2(hz, hw);
        ((__half2*)tb.l[sg])[2 * off] = __halves2half2(lx, ly);
        ((__half2*)tb.l[sg])[2 * off + 1] = __halves2half2(lz, lw);
    } else {
        ((__half2*)tb.h[sg])[2 * off] = __halves2half2(__float2half_rn(v.x), __float2half_rn(v.y));
        ((__half2*)tb.h[sg])[2 * off + 1] = __halves2half2(__float2half_rn(v.z), __float2half_rn(v.w));
    }
}

// ---------------- segment mean ----------------
__global__ void k_aggregate(const __half* __restrict__ Xh, const __half* __restrict__ Xl,
                            __half* __restrict__ Mh, __half* __restrict__ Ml) {
    const int d = blockIdx.x;
    const int t = threadIdx.x;
    const int beg = g_ROWPTR[d];
    const int end = g_ROWPTR[d + 1];
    float a0 = 0.f, a1 = 0.f, a2 = 0.f, a3 = 0.f;
    float b0 = 0.f, b1 = 0.f, b2 = 0.f, b3 = 0.f;
    int e = beg;
    for (; e + 1 < end; e += 2) {
        size_t o0 = (size_t)g_ESRC[e] * HID + t * 4;
        size_t o1 = (size_t)g_ESRC[e + 1] * HID + t * 4;
        float2 f;
        f = __half22float2(*(const __half2*)(Xh + o0));     a0 += f.x; a1 += f.y;
        f = __half22float2(*(const __half2*)(Xl + o0));     a0 += f.x; a1 += f.y;
        f = __half22float2(*(const __half2*)(Xh + o0 + 2)); a2 += f.x; a3 += f.y;
        f = __half22float2(*(const __half2*)(Xl + o0 + 2)); a2 += f.x; a3 += f.y;
        f = __half22float2(*(const __half2*)(Xh + o1));     b0 += f.x; b1 += f.y;
        f = __half22float2(*(const __half2*)(Xl + o1));     b0 += f.x; b1 += f.y;
        f = __half22float2(*(const __half2*)(Xh + o1 + 2)); b2 += f.x; b3 += f.y;
        f = __half22float2(*(const __half2*)(Xl + o1 + 2)); b2 += f.x; b3 += f.y;
    }
    if (e < end) {
        size_t o0 = (size_t)g_ESRC[e] * HID + t * 4;
        float2 f;
        f = __half22float2(*(const __half2*)(Xh + o0));     a0 += f.x; a1 += f.y;
        f = __half22float2(*(const __half2*)(Xl + o0));     a0 += f.x; a1 += f.y;
        f = __half22float2(*(const __half2*)(Xh + o0 + 2)); a2 += f.x; a3 += f.y;
        f = __half22float2(*(const __half2*)(Xl + o0 + 2)); a2 += f.x; a3 += f.y;
    }
    float inv = 1.0f / fmaxf((float)(end - beg), 1.0f);
    float m0 = (a0 + b0) * inv, m1 = (a1 + b1) * inv;
    float m2 = (a2 + b2) * inv, m3 = (a3 + b3) * inv;
    size_t o = (size_t)d * HID + t * 4;
    __half h0, h1, h2, h3, l0, l1, l2, l3;
    split_hl(m0, h0, l0); split_hl(m1, h1, l1);
    split_hl(m2, h2, l2); split_hl(m3, h3, l3);
    *(__half2*)(Mh + o) = __halves2half2(h0, h1);
    *(__half2*)(Mh + o + 2) = __halves2half2(h2, h3);
    *(__half2*)(Ml + o) = __halves2half2(l0, l1);
    *(__half2*)(Ml + o + 2) = __halves2half2(l2, l3);
}

// ---------------- persistent fused dual-term GEMM (fp16, 2 MMA terms) ----------------
// 128x128 tiles, 8 warps (2m x 4n), BK=64, 3 stages, stage = {Ah, Al, W}.
#define ROWB 144
#define TILE_SB (128 * ROWB)       // 18432
#define STAGE_SB (3 * TILE_SB)     // 55296
#define NSTAGE 3
#define BNOFF (NSTAGE * STAGE_SB)  // 165888
#define NEXTOFF (BNOFF + 1024)
#define GSMEM (NEXTOFF + 32)       // 166944
#define GTHR 256
#define NSM 148

__global__ void __launch_bounds__(GTHR, 1)
k_bgemm(const __half* __restrict__ a0h_r0, const __half* __restrict__ a0l_r0,
        const __half* __restrict__ w0_r0, int K0_r0,
        const __half* __restrict__ a0h_r1, const __half* __restrict__ a0l_r1,
        const __half* __restrict__ w0_r1, int K0_r1,
        const __half* __restrict__ a1h, const __half* __restrict__ a1l,
        const __half* __restrict__ w1, int K1,
        const float* __restrict__ bias_r0, const float* __restrict__ bias_r1,
        float* __restrict__ Cf, __half* __restrict__ Ch, __half* __restrict__ Cl,
        int N, int do_bn, int nx, int NT, int lfr, int qslot)
{
    extern __shared__ __align__(16) char smem[];
    const uint32_t sb = smem_u32(smem);
    const int tid = threadIdx.x;
    const int lane = tid & 31;
    const int wid = tid >> 5;
    const int wm = wid & 1;
    const int wn = wid >> 1;
    volatile int* nextp = (volatile int*)(smem + NEXTOFF);
    float* smS = (float*)(smem + BNOFF);
    float* smQ = smS + 128;

    auto geom = [&](int t, int& region, int& bml, int& bn, int& ncT, int& nc0) {
        int iy = t / nx, ix = t - iy * nx;
        int r = (iy < YTILES) ? lfr : (1 - lfr);
        region = r;
        bml = (iy < YTILES ? iy : iy - YTILES) * 128;
        bn = ix * 128;
        int K0 = r ? K0_r1 : K0_r0;
        nc0 = K0 >> 6;
        ncT = nc0 + ((r && K1 > 0) ? (K1 >> 6) : 0);
    };

    auto load_chunk = [&](int region, int bml, int bn, int nc0, int c, int slot) {
        const __half *ah, *al, *wp;
        int Ks, kof;
        if (c < nc0) {
            ah = region ? a0h_r1 : a0h_r0; al = region ? a0l_r1 : a0l_r0;
            wp = region ? w0_r1 : w0_r0;
            Ks = region ? K0_r1 : K0_r0; kof = c << 6;
        } else {
            ah = a1h; al = a1l; wp = w1; Ks = K1; kof = (c - nc0) << 6;
        }
        uint32_t st = sb + (uint32_t)slot * STAGE_SB;
        for (int i = tid; i < 1024; i += GTHR) {
            int r = i >> 3, cc = i & 7;
            uint32_t so = st + r * ROWB + cc * 16;
            int gml = bml + r;
            int sz = (gml < MREG) ? 16 : 0;
            size_t go = (size_t)(sz ? gml : 0) * Ks + kof + cc * 8;
            cpa(so, ah + go, sz);
            cpa(so + TILE_SB, al + go, sz);
            size_t gw = (size_t)(bn + r) * Ks + kof + cc * 8;
            cpa(so + 2 * TILE_SB, wp + gw, 16);
        }
        asm volatile("cp.async.commit_group;" ::: "memory");
    };

    if (tid == 0) *nextp = atomicAdd(&g_TQ[qslot], 1);
    __syncthreads();
    int t = *nextp;
    if (t >= NT) return;

    int region, bml, bn, ncT, nc0;
    geom(t, region, bml, bn, ncT, nc0);
    load_chunk(region, bml, bn, nc0, 0, 0);
    load_chunk(region, bml, bn, nc0, 1, 1);
    int gidx = 0;

    while (true) {
        float acc[4][4][4];
#pragma unroll
        for (int i = 0; i < 4; i++)
#pragma unroll
            for (int j = 0; j < 4; j++)
#pragma unroll
                for (int q = 0; q < 4; q++) acc[i][j][q] = 0.f;

        for (int c = 0; c < ncT; c++) {
            asm volatile("cp.async.wait_group 1;" ::: "memory");
            __syncthreads();
            if (c == 0 && tid == 0) *nextp = atomicAdd(&g_TQ[qslot], 1);
            {
                int pc = c + 2;
                int pslot = (gidx + 2) % NSTAGE;
                if (pc < ncT) {
                    load_chunk(region, bml, bn, nc0, pc, pslot);
                } else {
                    int tn = *nextp;
                    if (tn < NT) {
                        int r2, b2, n2, nt2, nc02;
                        geom(tn, r2, b2, n2, nt2, nc02);
                        load_chunk(r2, b2, n2, nc02, pc - ncT, pslot);
                    } else {
                        asm volatile("cp.async.commit_group;" ::: "memory");
                    }
                }
            }
            const uint32_t st = sb + (uint32_t)(gidx % NSTAGE) * STAGE_SB;
#pragma unroll
            for (int ks = 0; ks < 4; ks++) {
                uint32_t ah[4][4], al[4][4], bf[4][2];
                const int arow = wm * 64 + ((lane & 8) ? 8 : 0) + (lane & 7);
                const int acol = ks * 16 + ((lane & 16) ? 8 : 0);
#pragma unroll
                for (int mt = 0; mt < 4; mt++) {
                    uint32_t ad = st + (uint32_t)(arow + mt * 16) * ROWB + acol * 2;
                    ldm_x4(ah[mt], ad);
                    ldm_x4(al[mt], ad + TILE_SB);
                }
                const int brow = ((lane & 16) ? 8 : 0) + (lane & 7);
                const int bcol = ks * 16 + ((lane & 8) ? 8 : 0);
#pragma unroll
                for (int pr = 0; pr < 2; pr++) {
                    uint32_t tmp[4];
                    uint32_t bd = st + 2 * TILE_SB + (uint32_t)(wn * 32 + pr * 16 + brow) * ROWB + bcol * 2;
                    ldm_x4(tmp, bd);
                    bf[2 * pr][0] = tmp[0]; bf[2 * pr][1] = tmp[1];
                    bf[2 * pr + 1][0] = tmp[2]; bf[2 * pr + 1][1] = tmp[3];
                }
#pragma unroll
                for (int mt = 0; mt < 4; mt++)
#pragma unroll
                    for (int nt = 0; nt < 4; nt++)
                        mma_f16(acc[mt][nt], ah[mt], bf[nt]);
#pragma unroll
                for (int mt = 0; mt < 4; mt++)
#pragma unroll
                    for (int nt = 0; nt < 4; nt++)
                        mma_f16(acc[mt][nt], al[mt], bf[nt]);
            }
            gidx++;
        }

        // ---- epilogue ----
        if (do_bn) {
            if (tid < 128) { smS[tid] = 0.f; smQ[tid] = 0.f; }
            __syncthreads();
        }
        const float* bias = region ? bias_r1 : bias_r0;
        const int g = lane >> 2, tg = lane & 3;
        float bnS[4][2], bnQ[4][2];
#pragma unroll
        for (int nt = 0; nt < 4; nt++) { bnS[nt][0] = bnS[nt][1] = 0.f; bnQ[nt][0] = bnQ[nt][1] = 0.f; }

#pragma unroll
        for (int mt = 0; mt < 4; mt++)
#pragma unroll
            for (int h = 0; h < 2; h++) {
                const int gml = bml + wm * 64 + mt * 16 + g + h * 8;
                if (gml >= MREG) continue;
                const int grow = region * MREG + gml;
#pragma unroll
                for (int nt = 0; nt < 4; nt++) {
                    const int gn = bn + wn * 32 + nt * 8 + tg * 2;
                    float v0 = acc[mt][nt][h * 2 + 0];
                    float v1 = acc[mt][nt][h * 2 + 1];
                    if (bias) { v0 += __ldg(bias + gn); v1 += __ldg(bias + gn + 1); }
                    if (Cf) {
                        float2 vv; vv.x = v0; vv.y = v1;
                        *(float2*)(Cf + (size_t)grow * N + gn) = vv;
                    }
                    if (Ch) {
                        __half h0, h1, l0, l1;
                        split_hl(v0, h0, l0); split_hl(v1, h1, l1);
                        *(__half2*)(Ch + (size_t)grow * N + gn) = __halves2half2(h0, h1);
                        *(__half2*)(Cl + (size_t)grow * N + gn) = __halves2half2(l0, l1);
                    }
                    if (do_bn) {
                        bnS[nt][0] += v0; bnQ[nt][0] += v0 * v0;
                        bnS[nt][1] += v1; bnQ[nt][1] += v1 * v1;
                    }
                }
            }

        if (do_bn) {
#pragma unroll
            for (int nt = 0; nt < 4; nt++)
#pragma unroll
                for (int q = 0; q < 2; q++) {
                    float s = bnS[nt][q], qq = bnQ[nt][q];
#pragma unroll
                    for (int off = 4; off < 32; off <<= 1) {
                        s += __shfl_xor_sync(0xffffffffu, s, off);
                        qq += __shfl_xor_sync(0xffffffffu, qq, off);
                    }
                    if (g == 0) {
                        int cl = wn * 32 + nt * 8 + tg * 2 + q;
                        atomicAdd(&smS[cl], s);
                        atomicAdd(&smQ[cl], qq);
                    }
                }
            __syncthreads();
            if (tid < 128) {
                atomicAdd(&g_SUM[bn + tid], smS[tid]);
                atomicAdd(&g_SSQ[bn + tid], smQ[tid]);
            }
        }

        int tn = *nextp;
        if (tn >= NT) break;
        t = tn;
        geom(t, region, bml, bn, ncT, nc0);
    }
    asm volatile("cp.async.wait_group 0;" ::: "memory");
}

// ---------------- BatchNorm apply (+finalize inline) + ReLU -> AH/AL -----------------
__global__ void k_bnapply(const float* __restrict__ gamma, const float* __restrict__ beta) {
    size_t i = (size_t)blockIdx.x * blockDim.x + threadIdx.x;
    size_t base = i * 8;
    if (base >= (size_t)N_TOT * HID) return;
    int c = (int)(base & (HID - 1));
    const float inv_n = 1.0f / (float)N_TOT;
#pragma unroll
    for (int j = 0; j < 8; j += 2) {
        float mu0 = g_SUM[c + j] * inv_n;
        float var0 = g_SSQ[c + j] * inv_n - mu0 * mu0;
        float sc0 = __ldg(gamma + c + j) * rsqrtf(var0 + EPS);
        float sh0 = __ldg(beta + c + j) - mu0 * sc0;
        float mu1 = g_SUM[c + j + 1] * inv_n;
        float var1 = g_SSQ[c + j + 1] * inv_n - mu1 * mu1;
        float sc1 = __ldg(gamma + c + j + 1) * rsqrtf(var1 + EPS);
        float sh1 = __ldg(beta + c + j + 1) - mu1 * sc1;
        float2 hf = __half22float2(*(const __half2*)(g_X1H + base + j));
        float2 lf = __half22float2(*(const __half2*)(g_X1L + base + j));
        float x0 = hf.x + lf.x, x1 = hf.y + lf.y;
        float y0 = fmaxf(fmaf(x0, sc0, sh0), 0.f);
        float y1 = fmaxf(fmaf(x1, sc1, sh1), 0.f);
        __half h0, h1, l0, l1;
        split_hl(y0, h0, l0); split_hl(y1, h1, l1);
        *(__half2*)(g_AH + base + j) = __halves2half2(h0, h1);
        *(__half2*)(g_AL + base + j) = __halves2half2(l0, l1);
    }
}

// ---------------- launch ----------------
extern "C" void kernel_launch(void* const* d_in, const int* in_sizes, int n_in,
                              void* d_out, int out_size) {
    const float* x_src = (const float*)d_in[0];
    const float* x_dst = (const float*)d_in[1];
    const float* W_src = (const float*)d_in[2];
    const float* b_src = (const float*)d_in[3];
    const float* W_dst = (const float*)d_in[4];
    const float* b_dst = (const float*)d_in[5];
    const float* W1l   = (const float*)d_in[6];
    const float* b1    = (const float*)d_in[7];
    const float* W1r   = (const float*)d_in[8];
    const float* W2l   = (const float*)d_in[9];
    const float* b2    = (const float*)d_in[10];
    const float* W2r   = (const float*)d_in[11];
    const float* gamma = (const float*)d_in[12];
    const float* beta  = (const float*)d_in[13];
    const void*  ei    = (const void*)d_in[14];
    float* out = (float*)d_out;

    static int smem_set = 0;
    if (!smem_set) {
        cudaFuncSetAttribute(k_bgemm, cudaFuncAttributeMaxDynamicSharedMemorySize, GSMEM);
        smem_set = 1;
    }

    __half *AH, *AL, *X1H, *X1L, *MH, *ML, *XSH, *XSL, *XDH, *XDL;
    __half *WS, *WD, *W1L, *W1R, *W2L, *W2R;
    cudaGetSymbolAddress((void**)&AH, g_AH);   cudaGetSymbolAddress((void**)&AL, g_AL);
    cudaGetSymbolAddress((void**)&X1H, g_X1H); cudaGetSymbolAddress((void**)&X1L, g_X1L);
    cudaGetSymbolAddress((void**)&MH, g_MH);   cudaGetSymbolAddress((void**)&ML, g_ML);
    cudaGetSymbolAddress((void**)&XSH, g_XSH); cudaGetSymbolAddress((void**)&XSL, g_XSL);
    cudaGetSymbolAddress((void**)&XDH, g_XDH); cudaGetSymbolAddress((void**)&XDL, g_XDL);
    cudaGetSymbolAddress((void**)&WS, g_WS);   cudaGetSymbolAddress((void**)&WD, g_WD);
    cudaGetSymbolAddress((void**)&W1L, g_W1L); cudaGetSymbolAddress((void**)&W1R, g_W1R);
    cudaGetSymbolAddress((void**)&W2L, g_W2L); cudaGetSymbolAddress((void**)&W2R, g_W2R);

    k_init<<<(N_DST + 255) / 256, 256>>>((const int*)ei);
    k_decode_count<<<(N_EDGES + 255) / 256, 256>>>(ei);
    ConvTab tb;
    const float* srcs[8] = {W_src, W_dst, W1l, W1r, W2l, W2r, x_src, x_dst};
    __half* hs[8] = {WS, WD, W1L, W1R, W2L, W2R, XSH, XDH};
    __half* ls[8] = {nullptr, nullptr, nullptr, nullptr, nullptr, nullptr, XSL, XDL};
    int ns[8] = {HID * IN_SRC, HID * IN_DST, HID * HID, HID * HID, OUTD * HID, OUTD * HID,
                 N_SRC * IN_SRC, N_DST * IN_DST};
    int cum = 0;
    for (int j = 0; j < 8; j++) {
        tb.s[j] = srcs[j]; tb.h[j] = hs[j]; tb.l[j] = ls[j];
        cum += ns[j] / 4; tb.end[j] = cum;
    }
    k_conv_all<<<(cum + 255) / 256, 256>>>(tb);

    // fused projection GEMM -> AH/AL
    k_bgemm<<<NSM, GTHR, GSMEM>>>(XSH, XSL, WS, IN_SRC,
                                  XDH, XDL, WD, IN_DST,
                                  nullptr, nullptr, nullptr, 0,
                                  b_src, b_dst,
                                  nullptr, AH, AL, HID, 0,
                                  HID / 128, (HID / 128) * 2 * YTILES, 0, 0);

    // CSR finish
    k_scan<<<1, 1024>>>();
    k_fill<<<(N_EDGES + 255) / 256, 256>>>();

    // layer 1
    k_aggregate<<<N_DST, 128>>>(AH, AL, MH, ML);
    k_bgemm<<<NSM, GTHR, GSMEM>>>(AH, AL, W1R, HID,
                                  AH + (size_t)N_SRC * HID, AL + (size_t)N_SRC * HID, W1R, HID,
                                  MH, ML, W1L, HID,
                                  b1, b1,
                                  nullptr, X1H, X1L, HID, 1,
                                  HID / 128, (HID / 128) * 2 * YTILES, 1, 1);

    // BN (finalize inline) + ReLU
    k_bnapply<<<(int)(((size_t)N_TOT * HID / 8 + 255) / 256), 256>>>(gamma, beta);

    // layer 2
    k_aggregate<<<N_DST, 128>>>(AH, AL, MH, ML);
    k_bgemm<<<NSM, GTHR, GSMEM>>>(AH, AL, W2R, HID,
                                  AH + (size_t)N_SRC * HID, AL + (size_t)N_SRC * HID, W2R, HID,
                                  MH, ML, W2L, HID,
                                  b2, b2,
                                  out, nullptr, nullptr, OUTD, 0,
                                  OUTD / 128, (OUTD / 128) * 2 * YTILES, 1, 2);
}

// round 16
// speedup vs baseline: 1.0562x; 1.0562x over previous
#include <cuda_runtime.h>
#include <cuda_fp16.h>
#include <math.h>
#include <stdint.h>

#define N_SRC   10000
#define N_DST   10000
#define N_TOT   20000
#define IN_SRC  512
#define IN_DST  256
#define HID     512
#define OUTD    256
#define N_EDGES 160000
#define EPS     1e-5f
#define MREG    10000
#define YTILES  79

// ---------------- device scratch (fp16 hi/lo activations, fp16 single weights) --------
__device__ __align__(16) __half g_AH[(size_t)N_TOT * HID];
__device__ __align__(16) __half g_AL[(size_t)N_TOT * HID];
__device__ __align__(16) __half g_X1H[(size_t)N_TOT * HID];
__device__ __align__(16) __half g_X1L[(size_t)N_TOT * HID];
__device__ __align__(16) __half g_MH[(size_t)N_DST * HID];
__device__ __align__(16) __half g_ML[(size_t)N_DST * HID];
__device__ __align__(16) __half g_XSH[(size_t)N_SRC * IN_SRC], g_XSL[(size_t)N_SRC * IN_SRC];
__device__ __align__(16) __half g_XDH[(size_t)N_DST * IN_DST], g_XDL[(size_t)N_DST * IN_DST];
__device__ __align__(16) __half g_WS[HID * IN_SRC];
__device__ __align__(16) __half g_WD[HID * IN_DST];
__device__ __align__(16) __half g_W1L[HID * HID];
__device__ __align__(16) __half g_W1R[HID * HID];
__device__ __align__(16) __half g_W2L[OUTD * HID];
__device__ __align__(16) __half g_W2R[OUTD * HID];
__device__ int   g_SRC[N_EDGES];
__device__ int   g_DSTL[N_EDGES];
__device__ int   g_IS64;
__device__ int   g_CNT[N_DST];
__device__ int   g_ROWPTR[N_DST + 1];
__device__ int   g_CURSOR[N_DST];
__device__ int   g_ESRC[N_EDGES];
__device__ float g_SUM[HID];
__device__ float g_SSQ[HID];
__device__ float g_SCALE[HID];
__device__ float g_SHIFT[HID];
__device__ int   g_TQ[4];

// ---------------- helpers ----------------
__device__ __forceinline__ uint32_t smem_u32(const void* p) {
    uint32_t a;
    asm("{ .reg .u64 t; cvta.to.shared.u64 t, %1; cvt.u32.u64 %0, t; }" : "=r"(a) : "l"(p));
    return a;
}
__device__ __forceinline__ void cpa(uint32_t d, const void* s, int sz) {
    asm volatile("cp.async.cg.shared.global [%0], [%1], 16, %2;"
                 :: "r"(d), "l"(s), "r"(sz) : "memory");
}
__device__ __forceinline__ void ldm_x4(uint32_t* r, uint32_t a) {
    asm volatile("ldmatrix.sync.aligned.m8n8.x4.shared.b16 {%0,%1,%2,%3}, [%4];"
                 : "=r"(r[0]), "=r"(r[1]), "=r"(r[2]), "=r"(r[3]) : "r"(a));
}
__device__ __forceinline__ void mma_f16(float* d, const uint32_t* a, const uint32_t* b) {
    asm("mma.sync.aligned.m16n8k16.row.col.f32.f16.f16.f32 "
        "{%0,%1,%2,%3}, {%4,%5,%6,%7}, {%8,%9}, {%0,%1,%2,%3};"
        : "+f"(d[0]), "+f"(d[1]), "+f"(d[2]), "+f"(d[3])
        : "r"(a[0]), "r"(a[1]), "r"(a[2]), "r"(a[3]), "r"(b[0]), "r"(b[1]));
}
__device__ __forceinline__ void split_hl(float v, __half& h, __half& l) {
    h = __float2half_rn(v);
    l = __float2half_rn(v - __half2float(h));
}

// ---------------- init: zero counts + queues + BN accum + dtype detect ---------------
__global__ void k_init(const int* __restrict__ ei32) {
    int i = blockIdx.x * blockDim.x + threadIdx.x;
    if (i < N_DST) g_CNT[i] = 0;
    if (i < 4) g_TQ[i] = 0;
    if (i < HID) { g_SUM[i] = 0.f; g_SSQ[i] = 0.f; }
    if (blockIdx.x == 0 && threadIdx.x == 0) {
        int allzero = 1;
        for (int j = 0; j < 64; j++)
            if (ei32[2 * j + 1] != 0) { allzero = 0; break; }
        g_IS64 = allzero;
    }
}
// fused decode + histogram
__global__ void k_decode_count(const void* __restrict__ ei) {
    int e = blockIdx.x * blockDim.x + threadIdx.x;
    if (e >= N_EDGES) return;
    int s, d;
    if (g_IS64) {
        const long long* p = (const long long*)ei;
        s = (int)p[e]; d = (int)p[N_EDGES + e];
    } else {
        const int* p = (const int*)ei;
        s = p[e]; d = p[N_EDGES + e];
    }
    int dl = d - N_SRC;
    g_SRC[e] = s;
    g_DSTL[e] = dl;
    if (dl >= 0 && dl < N_DST) atomicAdd(&g_CNT[dl], 1);
}
__global__ void k_scan() {
    __shared__ int s[1024];
    const int t = threadIdx.x;
    const int base = t * 10;
    int vals[10];
    int local = 0;
#pragma unroll
    for (int i = 0; i < 10; i++) {
        int idx = base + i;
        int v = (idx < N_DST) ? g_CNT[idx] : 0;
        vals[i] = v; local += v;
    }
    s[t] = local;
    __syncthreads();
    for (int off = 1; off < 1024; off <<= 1) {
        int v = (t >= off) ? s[t - off] : 0;
        __syncthreads();
        s[t] += v;
        __syncthreads();
    }
    int run = (t == 0) ? 0 : s[t - 1];
#pragma unroll
    for (int i = 0; i < 10; i++) {
        int idx = base + i;
        if (idx < N_DST) { g_ROWPTR[idx] = run; g_CURSOR[idx] = run; run += vals[i]; }
    }
    if (t == 1023) g_ROWPTR[N_DST] = s[1023];
}
__global__ void k_fill() {
    int e = blockIdx.x * blockDim.x + threadIdx.x;
    if (e < N_EDGES) {
        int d = g_DSTL[e];
        int s = g_SRC[e];
        if (d >= 0 && d < N_DST && s >= 0 && s < N_TOT) {
            int pos = atomicAdd(&g_CURSOR[d], 1);
            if (pos < N_EDGES) g_ESRC[pos] = s;
        }
    }
}

// ---------------- batched fp32 -> fp16 conversion (split when l != null) -------------
struct ConvTab {
    const float* s[8];
    __half* h[8];
    __half* l[8];
    int end[8];
};
__global__ void k_conv_all(ConvTab tb) {
    int i = blockIdx.x * blockDim.x + threadIdx.x;
    if (i >= tb.end[7]) return;
    int sg = 0;
#pragma unroll
    for (int j = 0; j < 7; j++) sg += (i >= tb.end[j]);
    int base = sg ? tb.end[sg - 1] : 0;
    int off = i - base;
    float4 v = ((const float4*)tb.s[sg])[off];
    if (tb.l[sg]) {
        __half hx, hy, hz, hw, lx, ly, lz, lw;
        split_hl(v.x, hx, lx); split_hl(v.y, hy, ly);
        split_hl(v.z, hz, lz); split_hl(v.w, hw, lw);
        ((__half2*)tb.h[sg])[2 * off] = __halves2half2(hx, hy);
        ((__half2*)tb.h[sg])[2 * off + 1] = __halves2half2(hz, hw);
        ((__half2*)tb.l[sg])[2 * off] = __halves2half2(lx, ly);
        ((__half2*)tb.l[sg])[2 * off + 1] = __halves2half2(lz, lw);
    } else {
        ((__half2*)tb.h[sg])[2 * off] = __halves2half2(__float2half_rn(v.x), __float2half_rn(v.y));
        ((__half2*)tb.h[sg])[2 * off + 1] = __halves2half2(__float2half_rn(v.z), __float2half_rn(v.w));
    }
}

// ---------------- segment mean ----------------
__global__ void k_aggregate(const __half* __restrict__ Xh, const __half* __restrict__ Xl,
                            __half* __restrict__ Mh, __half* __restrict__ Ml) {
    const int d = blockIdx.x;
    const int t = threadIdx.x;
    const int beg = g_ROWPTR[d];
    const int end = g_ROWPTR[d + 1];
    float a0 = 0.f, a1 = 0.f, a2 = 0.f, a3 = 0.f;
    float b0 = 0.f, b1 = 0.f, b2 = 0.f, b3 = 0.f;
    int e = beg;
    for (; e + 1 < end; e += 2) {
        size_t o0 = (size_t)g_ESRC[e] * HID + t * 4;
        size_t o1 = (size_t)g_ESRC[e + 1] * HID + t * 4;
        float2 f;
        f = __half22float2(*(const __half2*)(Xh + o0));     a0 += f.x; a1 += f.y;
        f = __half22float2(*(const __half2*)(Xl + o0));     a0 += f.x; a1 += f.y;
        f = __half22float2(*(const __half2*)(Xh + o0 + 2)); a2 += f.x; a3 += f.y;
        f = __half22float2(*(const __half2*)(Xl + o0 + 2)); a2 += f.x; a3 += f.y;
        f = __half22float2(*(const __half2*)(Xh + o1));     b0 += f.x; b1 += f.y;
        f = __half22float2(*(const __half2*)(Xl + o1));     b0 += f.x; b1 += f.y;
        f = __half22float2(*(const __half2*)(Xh + o1 + 2)); b2 += f.x; b3 += f.y;
        f = __half22float2(*(const __half2*)(Xl + o1 + 2)); b2 += f.x; b3 += f.y;
    }
    if (e < end) {
        size_t o0 = (size_t)g_ESRC[e] * HID + t * 4;
        float2 f;
        f = __half22float2(*(const __half2*)(Xh + o0));     a0 += f.x; a1 += f.y;
        f = __half22float2(*(const __half2*)(Xl + o0));     a0 += f.x; a1 += f.y;
        f = __half22float2(*(const __half2*)(Xh + o0 + 2)); a2 += f.x; a3 += f.y;
        f = __half22float2(*(const __half2*)(Xl + o0 + 2)); a2 += f.x; a3 += f.y;
    }
    float inv = 1.0f / fmaxf((float)(end - beg), 1.0f);
    float m0 = (a0 + b0) * inv, m1 = (a1 + b1) * inv;
    float m2 = (a2 + b2) * inv, m3 = (a3 + b3) * inv;
    size_t o = (size_t)d * HID + t * 4;
    __half h0, h1, h2, h3, l0, l1, l2, l3;
    split_hl(m0, h0, l0); split_hl(m1, h1, l1);
    split_hl(m2, h2, l2); split_hl(m3, h3, l3);
    *(__half2*)(Mh + o) = __halves2half2(h0, h1);
    *(__half2*)(Mh + o + 2) = __halves2half2(h2, h3);
    *(__half2*)(Ml + o) = __halves2half2(l0, l1);
    *(__half2*)(Ml + o + 2) = __halves2half2(l2, l3);
}

// ---------------- persistent fused dual-term GEMM (fp16, 2 MMA terms) ----------------
// 128x128 tiles, 8 warps (2m x 4n), BK=64, 3 stages, stage = {Ah, Al, W}.
#define ROWB 144
#define TILE_SB (128 * ROWB)       // 18432
#define STAGE_SB (3 * TILE_SB)     // 55296
#define NSTAGE 3
#define BNOFF (NSTAGE * STAGE_SB)  // 165888
#define NEXTOFF (BNOFF + 1024)
#define GSMEM (NEXTOFF + 32)       // 166944
#define GTHR 256
#define NSM 148

__global__ void __launch_bounds__(GTHR, 1)
k_bgemm(const __half* __restrict__ a0h_r0, const __half* __restrict__ a0l_r0,
        const __half* __restrict__ w0_r0, int K0_r0,
        const __half* __restrict__ a0h_r1, const __half* __restrict__ a0l_r1,
        const __half* __restrict__ w0_r1, int K0_r1,
        const __half* __restrict__ a1h, const __half* __restrict__ a1l,
        const __half* __restrict__ w1, int K1,
        const float* __restrict__ bias_r0, const float* __restrict__ bias_r1,
        float* __restrict__ Cf, __half* __restrict__ Ch, __half* __restrict__ Cl,
        int N, int do_bn, int nx, int NT, int lfr, int qslot)
{
    extern __shared__ __align__(16) char smem[];
    const uint32_t sb = smem_u32(smem);
    const int tid = threadIdx.x;
    const int lane = tid & 31;
    const int wid = tid >> 5;
    const int wm = wid & 1;
    const int wn = wid >> 1;
    volatile int* nextp = (volatile int*)(smem + NEXTOFF);
    float* smS = (float*)(smem + BNOFF);
    float* smQ = smS + 128;

    auto geom = [&](int t, int& region, int& bml, int& bn, int& ncT, int& nc0) {
        int iy = t / nx, ix = t - iy * nx;
        int r = (iy < YTILES) ? lfr : (1 - lfr);
        region = r;
        bml = (iy < YTILES ? iy : iy - YTILES) * 128;
        bn = ix * 128;
        int K0 = r ? K0_r1 : K0_r0;
        nc0 = K0 >> 6;
        ncT = nc0 + ((r && K1 > 0) ? (K1 >> 6) : 0);
    };

    auto load_chunk = [&](int region, int bml, int bn, int nc0, int c, int slot) {
        const __half *ah, *al, *wp;
        int Ks, kof;
        if (c < nc0) {
            ah = region ? a0h_r1 : a0h_r0; al = region ? a0l_r1 : a0l_r0;
            wp = region ? w0_r1 : w0_r0;
            Ks = region ? K0_r1 : K0_r0; kof = c << 6;
        } else {
            ah = a1h; al = a1l; wp = w1; Ks = K1; kof = (c - nc0) << 6;
        }
        uint32_t st = sb + (uint32_t)slot * STAGE_SB;
        for (int i = tid; i < 1024; i += GTHR) {
            int r = i >> 3, cc = i & 7;
            uint32_t so = st + r * ROWB + cc * 16;
            int gml = bml + r;
            int sz = (gml < MREG) ? 16 : 0;
            size_t go = (size_t)(sz ? gml : 0) * Ks + kof + cc * 8;
            cpa(so, ah + go, sz);
            cpa(so + TILE_SB, al + go, sz);
            size_t gw = (size_t)(bn + r) * Ks + kof + cc * 8;
            cpa(so + 2 * TILE_SB, wp + gw, 16);
        }
        asm volatile("cp.async.commit_group;" ::: "memory");
    };

    if (tid == 0) *nextp = atomicAdd(&g_TQ[qslot], 1);
    __syncthreads();
    int t = *nextp;
    if (t >= NT) return;

    int region, bml, bn, ncT, nc0;
    geom(t, region, bml, bn, ncT, nc0);
    load_chunk(region, bml, bn, nc0, 0, 0);
    load_chunk(region, bml, bn, nc0, 1, 1);
    int gidx = 0;

    while (true) {
        float acc[4][4][4];
#pragma unroll
        for (int i = 0; i < 4; i++)
#pragma unroll
            for (int j = 0; j < 4; j++)
#pragma unroll
                for (int q = 0; q < 4; q++) acc[i][j][q] = 0.f;

        for (int c = 0; c < ncT; c++) {
            asm volatile("cp.async.wait_group 1;" ::: "memory");
            __syncthreads();
            if (c == 0 && tid == 0) *nextp = atomicAdd(&g_TQ[qslot], 1);
            {
                int pc = c + 2;
                int pslot = (gidx + 2) % NSTAGE;
                if (pc < ncT) {
                    load_chunk(region, bml, bn, nc0, pc, pslot);
                } else {
                    int tn = *nextp;
                    if (tn < NT) {
                        int r2, b2, n2, nt2, nc02;
                        geom(tn, r2, b2, n2, nt2, nc02);
                        load_chunk(r2, b2, n2, nc02, pc - ncT, pslot);
                    } else {
                        asm volatile("cp.async.commit_group;" ::: "memory");
                    }
                }
            }
            const uint32_t st = sb + (uint32_t)(gidx % NSTAGE) * STAGE_SB;
#pragma unroll
            for (int ks = 0; ks < 4; ks++) {
                uint32_t ah[4][4], al[4][4], bf[4][2];
                const int arow = wm * 64 + ((lane & 8) ? 8 : 0) + (lane & 7);
                const int acol = ks * 16 + ((lane & 16) ? 8 : 0);
#pragma unroll
                for (int mt = 0; mt < 4; mt++) {
                    uint32_t ad = st + (uint32_t)(arow + mt * 16) * ROWB + acol * 2;
                    ldm_x4(ah[mt], ad);
                    ldm_x4(al[mt], ad + TILE_SB);
                }
                const int brow = ((lane & 16) ? 8 : 0) + (lane & 7);
                const int bcol = ks * 16 + ((lane & 8) ? 8 : 0);
#pragma unroll
                for (int pr = 0; pr < 2; pr++) {
                    uint32_t tmp[4];
                    uint32_t bd = st + 2 * TILE_SB + (uint32_t)(wn * 32 + pr * 16 + brow) * ROWB + bcol * 2;
                    ldm_x4(tmp, bd);
                    bf[2 * pr][0] = tmp[0]; bf[2 * pr][1] = tmp[1];
                    bf[2 * pr + 1][0] = tmp[2]; bf[2 * pr + 1][1] = tmp[3];
                }
#pragma unroll
                for (int mt = 0; mt < 4; mt++)
#pragma unroll
                    for (int nt = 0; nt < 4; nt++)
                        mma_f16(acc[mt][nt], ah[mt], bf[nt]);
#pragma unroll
                for (int mt = 0; mt < 4; mt++)
#pragma unroll
                    for (int nt = 0; nt < 4; nt++)
                        mma_f16(acc[mt][nt], al[mt], bf[nt]);
            }
            gidx++;
        }

        // ---- epilogue ----
        if (do_bn) {
            if (tid < 128) { smS[tid] = 0.f; smQ[tid] = 0.f; }
            __syncthreads();
        }
        const float* bias = region ? bias_r1 : bias_r0;
        const int g = lane >> 2, tg = lane & 3;
        float bnS[4][2], bnQ[4][2];
#pragma unroll
        for (int nt = 0; nt < 4; nt++) { bnS[nt][0] = bnS[nt][1] = 0.f; bnQ[nt][0] = bnQ[nt][1] = 0.f; }

#pragma unroll
        for (int mt = 0; mt < 4; mt++)
#pragma unroll
            for (int h = 0; h < 2; h++) {
                const int gml = bml + wm * 64 + mt * 16 + g + h * 8;
                if (gml >= MREG) continue;
                const int grow = region * MREG + gml;
#pragma unroll
                for (int nt = 0; nt < 4; nt++) {
                    const int gn = bn + wn * 32 + nt * 8 + tg * 2;
                    float v0 = acc[mt][nt][h * 2 + 0];
                    float v1 = acc[mt][nt][h * 2 + 1];
                    if (bias) { v0 += __ldg(bias + gn); v1 += __ldg(bias + gn + 1); }
                    if (Cf) {
                        float2 vv; vv.x = v0; vv.y = v1;
                        *(float2*)(Cf + (size_t)grow * N + gn) = vv;
                    }
                    if (Ch) {
                        __half h0, h1, l0, l1;
                        split_hl(v0, h0, l0); split_hl(v1, h1, l1);
                        *(__half2*)(Ch + (size_t)grow * N + gn) = __halves2half2(h0, h1);
                        *(__half2*)(Cl + (size_t)grow * N + gn) = __halves2half2(l0, l1);
                    }
                    if (do_bn) {
                        bnS[nt][0] += v0; bnQ[nt][0] += v0 * v0;
                        bnS[nt][1] += v1; bnQ[nt][1] += v1 * v1;
                    }
                }
            }

        if (do_bn) {
#pragma unroll
            for (int nt = 0; nt < 4; nt++)
#pragma unroll
                for (int q = 0; q < 2; q++) {
                    float s = bnS[nt][q], qq = bnQ[nt][q];
#pragma unroll
                    for (int off = 4; off < 32; off <<= 1) {
                        s += __shfl_xor_sync(0xffffffffu, s, off);
                        qq += __shfl_xor_sync(0xffffffffu, qq, off);
                    }
                    if (g == 0) {
                        int cl = wn * 32 + nt * 8 + tg * 2 + q;
                        atomicAdd(&smS[cl], s);
                        atomicAdd(&smQ[cl], qq);
                    }
                }
            __syncthreads();
            if (tid < 128) {
                atomicAdd(&g_SUM[bn + tid], smS[tid]);
                atomicAdd(&g_SSQ[bn + tid], smQ[tid]);
            }
        }

        int tn = *nextp;
        if (tn >= NT) break;
        t = tn;
        geom(t, region, bml, bn, ncT, nc0);
    }
    asm volatile("cp.async.wait_group 0;" ::: "memory");
}

// ---------------- BatchNorm finalize (1 block) + apply ----------------
__global__ void k_bnfinal(const float* __restrict__ gamma, const float* __restrict__ beta) {
    int c = threadIdx.x;
    if (c < HID) {
        float mu = g_SUM[c] * (1.0f / (float)N_TOT);
        float var = g_SSQ[c] * (1.0f / (float)N_TOT) - mu * mu;
        float sc = gamma[c] * rsqrtf(var + EPS);
        g_SCALE[c] = sc;
        g_SHIFT[c] = beta[c] - mu * sc;
    }
}
__global__ void k_bnapply() {
    size_t i = (size_t)blockIdx.x * blockDim.x + threadIdx.x;
    size_t base = i * 8;
    if (base >= (size_t)N_TOT * HID) return;
    int c = (int)(base & (HID - 1));
#pragma unroll
    for (int j = 0; j < 8; j += 2) {
        float2 hf = __half22float2(*(const __half2*)(g_X1H + base + j));
        float2 lf = __half22float2(*(const __half2*)(g_X1L + base + j));
        float x0 = hf.x + lf.x, x1 = hf.y + lf.y;
        float y0 = fmaxf(fmaf(x0, g_SCALE[c + j], g_SHIFT[c + j]), 0.f);
        float y1 = fmaxf(fmaf(x1, g_SCALE[c + j + 1], g_SHIFT[c + j + 1]), 0.f);
        __half h0, h1, l0, l1;
        split_hl(y0, h0, l0); split_hl(y1, h1, l1);
        *(__half2*)(g_AH + base + j) = __halves2half2(h0, h1);
        *(__half2*)(g_AL + base + j) = __halves2half2(l0, l1);
    }
}

// ---------------- launch ----------------
extern "C" void kernel_launch(void* const* d_in, const int* in_sizes, int n_in,
                              void* d_out, int out_size) {
    const float* x_src = (const float*)d_in[0];
    const float* x_dst = (const float*)d_in[1];
    const float* W_src = (const float*)d_in[2];
    const float* b_src = (const float*)d_in[3];
    const float* W_dst = (const float*)d_in[4];
    const float* b_dst = (const float*)d_in[5];
    const float* W1l   = (const float*)d_in[6];
    const float* b1    = (const float*)d_in[7];
    const float* W1r   = (const float*)d_in[8];
    const float* W2l   = (const float*)d_in[9];
    const float* b2    = (const float*)d_in[10];
    const float* W2r   = (const float*)d_in[11];
    const float* gamma = (const float*)d_in[12];
    const float* beta  = (const float*)d_in[13];
    const void*  ei    = (const void*)d_in[14];
    float* out = (float*)d_out;

    static int smem_set = 0;
    if (!smem_set) {
        cudaFuncSetAttribute(k_bgemm, cudaFuncAttributeMaxDynamicSharedMemorySize, GSMEM);
        smem_set = 1;
    }

    __half *AH, *AL, *X1H, *X1L, *MH, *ML, *XSH, *XSL, *XDH, *XDL;
    __half *WS, *WD, *W1L, *W1R, *W2L, *W2R;
    cudaGetSymbolAddress((void**)&AH, g_AH);   cudaGetSymbolAddress((void**)&AL, g_AL);
    cudaGetSymbolAddress((void**)&X1H, g_X1H); cudaGetSymbolAddress((void**)&X1L, g_X1L);
    cudaGetSymbolAddress((void**)&MH, g_MH);   cudaGetSymbolAddress((void**)&ML, g_ML);
    cudaGetSymbolAddress((void**)&XSH, g_XSH); cudaGetSymbolAddress((void**)&XSL, g_XSL);
    cudaGetSymbolAddress((void**)&XDH, g_XDH); cudaGetSymbolAddress((void**)&XDL, g_XDL);
    cudaGetSymbolAddress((void**)&WS, g_WS);   cudaGetSymbolAddress((void**)&WD, g_WD);
    cudaGetSymbolAddress((void**)&W1L, g_W1L); cudaGetSymbolAddress((void**)&W1R, g_W1R);
    cudaGetSymbolAddress((void**)&W2L, g_W2L); cudaGetSymbolAddress((void**)&W2R, g_W2R);

    k_init<<<(N_DST + 255) / 256, 256>>>((const int*)ei);
    k_decode_count<<<(N_EDGES + 255) / 256, 256>>>(ei);
    ConvTab tb;
    const float* srcs[8] = {W_src, W_dst, W1l, W1r, W2l, W2r, x_src, x_dst};
    __half* hs[8] = {WS, WD, W1L, W1R, W2L, W2R, XSH, XDH};
    __half* ls[8] = {nullptr, nullptr, nullptr, nullptr, nullptr, nullptr, XSL, XDL};
    int ns[8] = {HID * IN_SRC, HID * IN_DST, HID * HID, HID * HID, OUTD * HID, OUTD * HID,
                 N_SRC * IN_SRC, N_DST * IN_DST};
    int cum = 0;
    for (int j = 0; j < 8; j++) {
        tb.s[j] = srcs[j]; tb.h[j] = hs[j]; tb.l[j] = ls[j];
        cum += ns[j] / 4; tb.end[j] = cum;
    }
    k_conv_all<<<(cum + 255) / 256, 256>>>(tb);

    // fused projection GEMM -> AH/AL
    k_bgemm<<<NSM, GTHR, GSMEM>>>(XSH, XSL, WS, IN_SRC,
                                  XDH, XDL, WD, IN_DST,
                                  nullptr, nullptr, nullptr, 0,
                                  b_src, b_dst,
                                  nullptr, AH, AL, HID, 0,
                                  HID / 128, (HID / 128) * 2 * YTILES, 0, 0);

    // CSR finish
    k_scan<<<1, 1024>>>();
    k_fill<<<(N_EDGES + 255) / 256, 256>>>();

    // layer 1
    k_aggregate<<<N_DST, 128>>>(AH, AL, MH, ML);
    k_bgemm<<<NSM, GTHR, GSMEM>>>(AH, AL, W1R, HID,
                                  AH + (size_t)N_SRC * HID, AL + (size_t)N_SRC * HID, W1R, HID,
                                  MH, ML, W1L, HID,
                                  b1, b1,
                                  nullptr, X1H, X1L, HID, 1,
                                  HID / 128, (HID / 128) * 2 * YTILES, 1, 1);

    // BN finalize + apply (+ReLU)
    k_bnfinal<<<1, 512>>>(gamma, beta);
    k_bnapply<<<(int)(((size_t)N_TOT * HID / 8 + 255) / 256), 256>>>();

    // layer 2
    k_aggregate<<<N_DST, 128>>>(AH, AL, MH, ML);
    k_bgemm<<<NSM, GTHR, GSMEM>>>(AH, AL, W2R, HID,
                                  AH + (size_t)N_SRC * HID, AL + (size_t)N_SRC * HID, W2R, HID,
                                  MH, ML, W2L, HID,
                                  b2, b2,
                                  out, nullptr, nullptr, OUTD, 0,
                                  OUTD / 128, (OUTD / 128) * 2 * YTILES, 1, 2);
}

// round 17
// speedup vs baseline: 1.1463x; 1.0853x over previous
#include <cuda_runtime.h>
#include <cuda_fp16.h>
#include <math.h>
#include <stdint.h>

#define N_SRC   10000
#define N_DST   10000
#define N_TOT   20000
#define IN_SRC  512
#define IN_DST  256
#define HID     512
#define OUTD    256
#define N_EDGES 160000
#define EPS     1e-5f
#define MREG    10000
#define YTILES  79

// ---------------- device scratch (fp16 hi/lo activations, fp16 single weights) --------
__device__ __align__(16) __half g_AH[(size_t)N_TOT * HID];
__device__ __align__(16) __half g_AL[(size_t)N_TOT * HID];
__device__ __align__(16) __half g_X1H[(size_t)N_TOT * HID];
__device__ __align__(16) __half g_X1L[(size_t)N_TOT * HID];
__device__ __align__(16) __half g_MH[(size_t)N_DST * HID];
__device__ __align__(16) __half g_ML[(size_t)N_DST * HID];
__device__ __align__(16) __half g_XSH[(size_t)N_SRC * IN_SRC], g_XSL[(size_t)N_SRC * IN_SRC];
__device__ __align__(16) __half g_XDH[(size_t)N_DST * IN_DST], g_XDL[(size_t)N_DST * IN_DST];
__device__ __align__(16) __half g_WS[HID * IN_SRC];
__device__ __align__(16) __half g_WD[HID * IN_DST];
__device__ __align__(16) __half g_W1L[HID * HID];
__device__ __align__(16) __half g_W1R[HID * HID];
__device__ __align__(16) __half g_W2L[OUTD * HID];
__device__ __align__(16) __half g_W2R[OUTD * HID];
__device__ int   g_SRC[N_EDGES];
__device__ int   g_DSTL[N_EDGES];
__device__ int   g_IS64;
__device__ int   g_CNT[N_DST];
__device__ int   g_ROWPTR[N_DST + 1];
__device__ int   g_CURSOR[N_DST];
__device__ int   g_ESRC[N_EDGES];
__device__ float g_SUM[HID];
__device__ float g_SSQ[HID];
__device__ float g_SCALE[HID];
__device__ float g_SHIFT[HID];
__device__ int   g_TQ[4];

// ---------------- helpers ----------------
__device__ __forceinline__ uint32_t smem_u32(const void* p) {
    uint32_t a;
    asm("{ .reg .u64 t; cvta.to.shared.u64 t, %1; cvt.u32.u64 %0, t; }" : "=r"(a) : "l"(p));
    return a;
}
__device__ __forceinline__ void cpa(uint32_t d, const void* s, int sz) {
    asm volatile("cp.async.cg.shared.global [%0], [%1], 16, %2;"
                 :: "r"(d), "l"(s), "r"(sz) : "memory");
}
__device__ __forceinline__ void ldm_x4(uint32_t* r, uint32_t a) {
    asm volatile("ldmatrix.sync.aligned.m8n8.x4.shared.b16 {%0,%1,%2,%3}, [%4];"
                 : "=r"(r[0]), "=r"(r[1]), "=r"(r[2]), "=r"(r[3]) : "r"(a));
}
__device__ __forceinline__ void mma_f16(float* d, const uint32_t* a, const uint32_t* b) {
    asm("mma.sync.aligned.m16n8k16.row.col.f32.f16.f16.f32 "
        "{%0,%1,%2,%3}, {%4,%5,%6,%7}, {%8,%9}, {%0,%1,%2,%3};"
        : "+f"(d[0]), "+f"(d[1]), "+f"(d[2]), "+f"(d[3])
        : "r"(a[0]), "r"(a[1]), "r"(a[2]), "r"(a[3]), "r"(b[0]), "r"(b[1]));
}
__device__ __forceinline__ void split_hl(float v, __half& h, __half& l) {
    h = __float2half_rn(v);
    l = __float2half_rn(v - __half2float(h));
}

// ---------------- init ----------------
__global__ void k_init(const int* __restrict__ ei32) {
    int i = blockIdx.x * blockDim.x + threadIdx.x;
    if (i < N_DST) g_CNT[i] = 0;
    if (i < 4) g_TQ[i] = 0;
    if (i < HID) { g_SUM[i] = 0.f; g_SSQ[i] = 0.f; }
    if (blockIdx.x == 0 && threadIdx.x == 0) {
        int allzero = 1;
        for (int j = 0; j < 64; j++)
            if (ei32[2 * j + 1] != 0) { allzero = 0; break; }
        g_IS64 = allzero;
    }
}
__global__ void k_decode_count(const void* __restrict__ ei) {
    int e = blockIdx.x * blockDim.x + threadIdx.x;
    if (e >= N_EDGES) return;
    int s, d;
    if (g_IS64) {
        const long long* p = (const long long*)ei;
        s = (int)p[e]; d = (int)p[N_EDGES + e];
    } else {
        const int* p = (const int*)ei;
        s = p[e]; d = p[N_EDGES + e];
    }
    int dl = d - N_SRC;
    g_SRC[e] = s;
    g_DSTL[e] = dl;
    if (dl >= 0 && dl < N_DST) atomicAdd(&g_CNT[dl], 1);
}
__global__ void k_scan() {
    __shared__ int s[1024];
    const int t = threadIdx.x;
    const int base = t * 10;
    int vals[10];
    int local = 0;
#pragma unroll
    for (int i = 0; i < 10; i++) {
        int idx = base + i;
        int v = (idx < N_DST) ? g_CNT[idx] : 0;
        vals[i] = v; local += v;
    }
    s[t] = local;
    __syncthreads();
    for (int off = 1; off < 1024; off <<= 1) {
        int v = (t >= off) ? s[t - off] : 0;
        __syncthreads();
        s[t] += v;
        __syncthreads();
    }
    int run = (t == 0) ? 0 : s[t - 1];
#pragma unroll
    for (int i = 0; i < 10; i++) {
        int idx = base + i;
        if (idx < N_DST) { g_ROWPTR[idx] = run; g_CURSOR[idx] = run; run += vals[i]; }
    }
    if (t == 1023) g_ROWPTR[N_DST] = s[1023];
}
__global__ void k_fill() {
    int e = blockIdx.x * blockDim.x + threadIdx.x;
    if (e < N_EDGES) {
        int d = g_DSTL[e];
        int s = g_SRC[e];
        if (d >= 0 && d < N_DST && s >= 0 && s < N_TOT) {
            int pos = atomicAdd(&g_CURSOR[d], 1);
            if (pos < N_EDGES) g_ESRC[pos] = s;
        }
    }
}

// ---------------- batched fp32 -> fp16 conversion (split when l != null) -------------
struct ConvTab {
    const float* s[8];
    __half* h[8];
    __half* l[8];
    int end[8];
};
__global__ void k_conv_all(ConvTab tb) {
    int i = blockIdx.x * blockDim.x + threadIdx.x;
    if (i >= tb.end[7]) return;
    int sg = 0;
#pragma unroll
    for (int j = 0; j < 7; j++) sg += (i >= tb.end[j]);
    int base = sg ? tb.end[sg - 1] : 0;
    int off = i - base;
    float4 v = ((const float4*)tb.s[sg])[off];
    if (tb.l[sg]) {
        __half hx, hy, hz, hw, lx, ly, lz, lw;
        split_hl(v.x, hx, lx); split_hl(v.y, hy, ly);
        split_hl(v.z, hz, lz); split_hl(v.w, hw, lw);
        ((__half2*)tb.h[sg])[2 * off] = __halves2half2(hx, hy);
        ((__half2*)tb.h[sg])[2 * off + 1] = __halves2half2(hz, hw);
        ((__half2*)tb.l[sg])[2 * off] = __halves2half2(lx, ly);
        ((__half2*)tb.l[sg])[2 * off + 1] = __halves2half2(lz, lw);
    } else {
        ((__half2*)tb.h[sg])[2 * off] = __halves2half2(__float2half_rn(v.x), __float2half_rn(v.y));
        ((__half2*)tb.h[sg])[2 * off + 1] = __halves2half2(__float2half_rn(v.z), __float2half_rn(v.w));
    }
}

// ---------------- segment mean (Xl / Ml nullable) ----------------
__global__ void k_aggregate(const __half* __restrict__ Xh, const __half* __restrict__ Xl,
                            __half* __restrict__ Mh, __half* __restrict__ Ml) {
    const int d = blockIdx.x;
    const int t = threadIdx.x;
    const int beg = g_ROWPTR[d];
    const int end = g_ROWPTR[d + 1];
    const bool uselo = (Xl != nullptr);
    float a0 = 0.f, a1 = 0.f, a2 = 0.f, a3 = 0.f;
    float b0 = 0.f, b1 = 0.f, b2 = 0.f, b3 = 0.f;
    int e = beg;
    for (; e + 1 < end; e += 2) {
        size_t o0 = (size_t)g_ESRC[e] * HID + t * 4;
        size_t o1 = (size_t)g_ESRC[e + 1] * HID + t * 4;
        float2 f;
        f = __half22float2(*(const __half2*)(Xh + o0));     a0 += f.x; a1 += f.y;
        f = __half22float2(*(const __half2*)(Xh + o0 + 2)); a2 += f.x; a3 += f.y;
        f = __half22float2(*(const __half2*)(Xh + o1));     b0 += f.x; b1 += f.y;
        f = __half22float2(*(const __half2*)(Xh + o1 + 2)); b2 += f.x; b3 += f.y;
        if (uselo) {
            f = __half22float2(*(const __half2*)(Xl + o0));     a0 += f.x; a1 += f.y;
            f = __half22float2(*(const __half2*)(Xl + o0 + 2)); a2 += f.x; a3 += f.y;
            f = __half22float2(*(const __half2*)(Xl + o1));     b0 += f.x; b1 += f.y;
            f = __half22float2(*(const __half2*)(Xl + o1 + 2)); b2 += f.x; b3 += f.y;
        }
    }
    if (e < end) {
        size_t o0 = (size_t)g_ESRC[e] * HID + t * 4;
        float2 f;
        f = __half22float2(*(const __half2*)(Xh + o0));     a0 += f.x; a1 += f.y;
        f = __half22float2(*(const __half2*)(Xh + o0 + 2)); a2 += f.x; a3 += f.y;
        if (uselo) {
            f = __half22float2(*(const __half2*)(Xl + o0));     a0 += f.x; a1 += f.y;
            f = __half22float2(*(const __half2*)(Xl + o0 + 2)); a2 += f.x; a3 += f.y;
        }
    }
    float inv = 1.0f / fmaxf((float)(end - beg), 1.0f);
    float m0 = (a0 + b0) * inv, m1 = (a1 + b1) * inv;
    float m2 = (a2 + b2) * inv, m3 = (a3 + b3) * inv;
    size_t o = (size_t)d * HID + t * 4;
    __half h0, h1, h2, h3, l0, l1, l2, l3;
    split_hl(m0, h0, l0); split_hl(m1, h1, l1);
    split_hl(m2, h2, l2); split_hl(m3, h3, l3);
    *(__half2*)(Mh + o) = __halves2half2(h0, h1);
    *(__half2*)(Mh + o + 2) = __halves2half2(h2, h3);
    if (Ml) {
        *(__half2*)(Ml + o) = __halves2half2(l0, l1);
        *(__half2*)(Ml + o + 2) = __halves2half2(l2, l3);
    }
}

// ---------------- persistent fused dual-term GEMM (fp16, 1 or 2 MMA terms) -----------
// 128x128 tiles, 8 warps (2m x 4n), BK=64, 3 stages, stage = {Ah, Al, W}.
#define ROWB 144
#define TILE_SB (128 * ROWB)       // 18432
#define STAGE_SB (3 * TILE_SB)     // 55296
#define NSTAGE 3
#define BNOFF (NSTAGE * STAGE_SB)  // 165888
#define NEXTOFF (BNOFF + 1024)
#define GSMEM (NEXTOFF + 32)       // 166944
#define GTHR 256
#define NSM 148

__global__ void __launch_bounds__(GTHR, 1)
k_bgemm(const __half* __restrict__ a0h_r0, const __half* __restrict__ a0l_r0,
        const __half* __restrict__ w0_r0, int K0_r0,
        const __half* __restrict__ a0h_r1, const __half* __restrict__ a0l_r1,
        const __half* __restrict__ w0_r1, int K0_r1,
        const __half* __restrict__ a1h, const __half* __restrict__ a1l,
        const __half* __restrict__ w1, int K1,
        const float* __restrict__ bias_r0, const float* __restrict__ bias_r1,
        float* __restrict__ Cf, __half* __restrict__ Ch, __half* __restrict__ Cl,
        int N, int do_bn, int nx, int NT, int lfr, int qslot, int terms)
{
    extern __shared__ __align__(16) char smem[];
    const uint32_t sb = smem_u32(smem);
    const int tid = threadIdx.x;
    const int lane = tid & 31;
    const int wid = tid >> 5;
    const int wm = wid & 1;
    const int wn = wid >> 1;
    volatile int* nextp = (volatile int*)(smem + NEXTOFF);
    float* smS = (float*)(smem + BNOFF);
    float* smQ = smS + 128;

    auto geom = [&](int t, int& region, int& bml, int& bn, int& ncT, int& nc0) {
        int iy = t / nx, ix = t - iy * nx;
        int r = (iy < YTILES) ? lfr : (1 - lfr);
        region = r;
        bml = (iy < YTILES ? iy : iy - YTILES) * 128;
        bn = ix * 128;
        int K0 = r ? K0_r1 : K0_r0;
        nc0 = K0 >> 6;
        ncT = nc0 + ((r && K1 > 0) ? (K1 >> 6) : 0);
    };

    auto load_chunk = [&](int region, int bml, int bn, int nc0, int c, int slot) {
        const __half *ah, *al, *wp;
        int Ks, kof;
        if (c < nc0) {
            ah = region ? a0h_r1 : a0h_r0; al = region ? a0l_r1 : a0l_r0;
            wp = region ? w0_r1 : w0_r0;
            Ks = region ? K0_r1 : K0_r0; kof = c << 6;
        } else {
            ah = a1h; al = a1l; wp = w1; Ks = K1; kof = (c - nc0) << 6;
        }
        uint32_t st = sb + (uint32_t)slot * STAGE_SB;
        for (int i = tid; i < 1024; i += GTHR) {
            int r = i >> 3, cc = i & 7;
            uint32_t so = st + r * ROWB + cc * 16;
            int gml = bml + r;
            int sz = (gml < MREG) ? 16 : 0;
            size_t go = (size_t)(sz ? gml : 0) * Ks + kof + cc * 8;
            cpa(so, ah + go, sz);
            if (terms == 2) cpa(so + TILE_SB, al + go, sz);
            size_t gw = (size_t)(bn + r) * Ks + kof + cc * 8;
            cpa(so + 2 * TILE_SB, wp + gw, 16);
        }
        asm volatile("cp.async.commit_group;" ::: "memory");
    };

    if (tid == 0) *nextp = atomicAdd(&g_TQ[qslot], 1);
    __syncthreads();
    int t = *nextp;
    if (t >= NT) return;

    int region, bml, bn, ncT, nc0;
    geom(t, region, bml, bn, ncT, nc0);
    load_chunk(region, bml, bn, nc0, 0, 0);
    load_chunk(region, bml, bn, nc0, 1, 1);
    int gidx = 0;

    while (true) {
        float acc[4][4][4];
#pragma unroll
        for (int i = 0; i < 4; i++)
#pragma unroll
            for (int j = 0; j < 4; j++)
#pragma unroll
                for (int q = 0; q < 4; q++) acc[i][j][q] = 0.f;

        for (int c = 0; c < ncT; c++) {
            asm volatile("cp.async.wait_group 1;" ::: "memory");
            __syncthreads();
            if (c == 0 && tid == 0) *nextp = atomicAdd(&g_TQ[qslot], 1);
            {
                int pc = c + 2;
                int pslot = (gidx + 2) % NSTAGE;
                if (pc < ncT) {
                    load_chunk(region, bml, bn, nc0, pc, pslot);
                } else {
                    int tn = *nextp;
                    if (tn < NT) {
                        int r2, b2, n2, nt2, nc02;
                        geom(tn, r2, b2, n2, nt2, nc02);
                        load_chunk(r2, b2, n2, nc02, pc - ncT, pslot);
                    } else {
                        asm volatile("cp.async.commit_group;" ::: "memory");
                    }
                }
            }
            const uint32_t st = sb + (uint32_t)(gidx % NSTAGE) * STAGE_SB;
#pragma unroll
            for (int ks = 0; ks < 4; ks++) {
                uint32_t ah[4][4], al[4][4], bf[4][2];
                const int arow = wm * 64 + ((lane & 8) ? 8 : 0) + (lane & 7);
                const int acol = ks * 16 + ((lane & 16) ? 8 : 0);
#pragma unroll
                for (int mt = 0; mt < 4; mt++) {
                    uint32_t ad = st + (uint32_t)(arow + mt * 16) * ROWB + acol * 2;
                    ldm_x4(ah[mt], ad);
                    if (terms == 2) ldm_x4(al[mt], ad + TILE_SB);
                }
                const int brow = ((lane & 16) ? 8 : 0) + (lane & 7);
                const int bcol = ks * 16 + ((lane & 8) ? 8 : 0);
#pragma unroll
                for (int pr = 0; pr < 2; pr++) {
                    uint32_t tmp[4];
                    uint32_t bd = st + 2 * TILE_SB + (uint32_t)(wn * 32 + pr * 16 + brow) * ROWB + bcol * 2;
                    ldm_x4(tmp, bd);
                    bf[2 * pr][0] = tmp[0]; bf[2 * pr][1] = tmp[1];
                    bf[2 * pr + 1][0] = tmp[2]; bf[2 * pr + 1][1] = tmp[3];
                }
#pragma unroll
                for (int mt = 0; mt < 4; mt++)
#pragma unroll
                    for (int nt = 0; nt < 4; nt++)
                        mma_f16(acc[mt][nt], ah[mt], bf[nt]);
                if (terms == 2) {
#pragma unroll
                    for (int mt = 0; mt < 4; mt++)
#pragma unroll
                        for (int nt = 0; nt < 4; nt++)
                            mma_f16(acc[mt][nt], al[mt], bf[nt]);
                }
            }
            gidx++;
        }

        // ---- epilogue ----
        if (do_bn) {
            if (tid < 128) { smS[tid] = 0.f; smQ[tid] = 0.f; }
            __syncthreads();
        }
        const float* bias = region ? bias_r1 : bias_r0;
        const int g = lane >> 2, tg = lane & 3;
        float bnS[4][2], bnQ[4][2];
#pragma unroll
        for (int nt = 0; nt < 4; nt++) { bnS[nt][0] = bnS[nt][1] = 0.f; bnQ[nt][0] = bnQ[nt][1] = 0.f; }

#pragma unroll
        for (int mt = 0; mt < 4; mt++)
#pragma unroll
            for (int h = 0; h < 2; h++) {
                const int gml = bml + wm * 64 + mt * 16 + g + h * 8;
                if (gml >= MREG) continue;
                const int grow = region * MREG + gml;
#pragma unroll
                for (int nt = 0; nt < 4; nt++) {
                    const int gn = bn + wn * 32 + nt * 8 + tg * 2;
                    float v0 = acc[mt][nt][h * 2 + 0];
                    float v1 = acc[mt][nt][h * 2 + 1];
                    if (bias) { v0 += __ldg(bias + gn); v1 += __ldg(bias + gn + 1); }
                    if (Cf) {
                        float2 vv; vv.x = v0; vv.y = v1;
                        *(float2*)(Cf + (size_t)grow * N + gn) = vv;
                    }
                    if (Ch) {
                        __half h0, h1, l0, l1;
                        split_hl(v0, h0, l0); split_hl(v1, h1, l1);
                        *(__half2*)(Ch + (size_t)grow * N + gn) = __halves2half2(h0, h1);
                        *(__half2*)(Cl + (size_t)grow * N + gn) = __halves2half2(l0, l1);
                    }
                    if (do_bn) {
                        bnS[nt][0] += v0; bnQ[nt][0] += v0 * v0;
                        bnS[nt][1] += v1; bnQ[nt][1] += v1 * v1;
                    }
                }
            }

        if (do_bn) {
#pragma unroll
            for (int nt = 0; nt < 4; nt++)
#pragma unroll
                for (int q = 0; q < 2; q++) {
                    float s = bnS[nt][q], qq = bnQ[nt][q];
#pragma unroll
                    for (int off = 4; off < 32; off <<= 1) {
                        s += __shfl_xor_sync(0xffffffffu, s, off);
                        qq += __shfl_xor_sync(0xffffffffu, qq, off);
                    }
                    if (g == 0) {
                        int cl = wn * 32 + nt * 8 + tg * 2 + q;
                        atomicAdd(&smS[cl], s);
                        atomicAdd(&smQ[cl], qq);
                    }
                }
            __syncthreads();
            if (tid < 128) {
                atomicAdd(&g_SUM[bn + tid], smS[tid]);
                atomicAdd(&g_SSQ[bn + tid], smQ[tid]);
            }
        }

        int tn = *nextp;
        if (tn >= NT) break;
        t = tn;
        geom(t, region, bml, bn, ncT, nc0);
    }
    asm volatile("cp.async.wait_group 0;" ::: "memory");
}

// ---------------- BatchNorm finalize (1 block) + apply ----------------
__global__ void k_bnfinal(const float* __restrict__ gamma, const float* __restrict__ beta) {
    int c = threadIdx.x;
    if (c < HID) {
        float mu = g_SUM[c] * (1.0f / (float)N_TOT);
        float var = g_SSQ[c] * (1.0f / (float)N_TOT) - mu * mu;
        float sc = gamma[c] * rsqrtf(var + EPS);
        g_SCALE[c] = sc;
        g_SHIFT[c] = beta[c] - mu * sc;
    }
}
// BN apply + ReLU -> AH only (layer 2 is single-fp16)
__global__ void k_bnapply() {
    size_t i = (size_t)blockIdx.x * blockDim.x + threadIdx.x;
    size_t base = i * 8;
    if (base >= (size_t)N_TOT * HID) return;
    int c = (int)(base & (HID - 1));
#pragma unroll
    for (int j = 0; j < 8; j += 2) {
        float2 hf = __half22float2(*(const __half2*)(g_X1H + base + j));
        float2 lf = __half22float2(*(const __half2*)(g_X1L + base + j));
        float x0 = hf.x + lf.x, x1 = hf.y + lf.y;
        float y0 = fmaxf(fmaf(x0, g_SCALE[c + j], g_SHIFT[c + j]), 0.f);
        float y1 = fmaxf(fmaf(x1, g_SCALE[c + j + 1], g_SHIFT[c + j + 1]), 0.f);
        *(__half2*)(g_AH + base + j) = __halves2half2(__float2half_rn(y0), __float2half_rn(y1));
    }
}

// ---------------- launch ----------------
extern "C" void kernel_launch(void* const* d_in, const int* in_sizes, int n_in,
                              void* d_out, int out_size) {
    const float* x_src = (const float*)d_in[0];
    const float* x_dst = (const float*)d_in[1];
    const float* W_src = (const float*)d_in[2];
    const float* b_src = (const float*)d_in[3];
    const float* W_dst = (const float*)d_in[4];
    const float* b_dst = (const float*)d_in[5];
    const float* W1l   = (const float*)d_in[6];
    const float* b1    = (const float*)d_in[7];
    const float* W1r   = (const float*)d_in[8];
    const float* W2l   = (const float*)d_in[9];
    const float* b2    = (const float*)d_in[10];
    const float* W2r   = (const float*)d_in[11];
    const float* gamma = (const float*)d_in[12];
    const float* beta  = (const float*)d_in[13];
    const void*  ei    = (const void*)d_in[14];
    float* out = (float*)d_out;

    static int smem_set = 0;
    if (!smem_set) {
        cudaFuncSetAttribute(k_bgemm, cudaFuncAttributeMaxDynamicSharedMemorySize, GSMEM);
        smem_set = 1;
    }

    __half *AH, *AL, *X1H, *X1L, *MH, *ML, *XSH, *XSL, *XDH, *XDL;
    __half *WS, *WD, *W1L, *W1R, *W2L, *W2R;
    cudaGetSymbolAddress((void**)&AH, g_AH);   cudaGetSymbolAddress((void**)&AL, g_AL);
    cudaGetSymbolAddress((void**)&X1H, g_X1H); cudaGetSymbolAddress((void**)&X1L, g_X1L);
    cudaGetSymbolAddress((void**)&MH, g_MH);   cudaGetSymbolAddress((void**)&ML, g_ML);
    cudaGetSymbolAddress((void**)&XSH, g_XSH); cudaGetSymbolAddress((void**)&XSL, g_XSL);
    cudaGetSymbolAddress((void**)&XDH, g_XDH); cudaGetSymbolAddress((void**)&XDL, g_XDL);
    cudaGetSymbolAddress((void**)&WS, g_WS);   cudaGetSymbolAddress((void**)&WD, g_WD);
    cudaGetSymbolAddress((void**)&W1L, g_W1L); cudaGetSymbolAddress((void**)&W1R, g_W1R);
    cudaGetSymbolAddress((void**)&W2L, g_W2L); cudaGetSymbolAddress((void**)&W2R, g_W2R);

    k_init<<<(N_DST + 255) / 256, 256>>>((const int*)ei);
    k_decode_count<<<(N_EDGES + 255) / 256, 256>>>(ei);
    ConvTab tb;
    const float* srcs[8] = {W_src, W_dst, W1l, W1r, W2l, W2r, x_src, x_dst};
    __half* hs[8] = {WS, WD, W1L, W1R, W2L, W2R, XSH, XDH};
    __half* ls[8] = {nullptr, nullptr, nullptr, nullptr, nullptr, nullptr, XSL, XDL};
    int ns[8] = {HID * IN_SRC, HID * IN_DST, HID * HID, HID * HID, OUTD * HID, OUTD * HID,
                 N_SRC * IN_SRC, N_DST * IN_DST};
    int cum = 0;
    for (int j = 0; j < 8; j++) {
        tb.s[j] = srcs[j]; tb.h[j] = hs[j]; tb.l[j] = ls[j];
        cum += ns[j] / 4; tb.end[j] = cum;
    }
    k_conv_all<<<(cum + 255) / 256, 256>>>(tb);

    // fused projection GEMM -> AH/AL (2-term)
    k_bgemm<<<NSM, GTHR, GSMEM>>>(XSH, XSL, WS, IN_SRC,
                                  XDH, XDL, WD, IN_DST,
                                  nullptr, nullptr, nullptr, 0,
                                  b_src, b_dst,
                                  nullptr, AH, AL, HID, 0,
                                  HID / 128, (HID / 128) * 2 * YTILES, 0, 0, 2);

    // CSR finish
    k_scan<<<1, 1024>>>();
    k_fill<<<(N_EDGES + 255) / 256, 256>>>();

    // layer 1 (2-term, full precision)
    k_aggregate<<<N_DST, 128>>>(AH, AL, MH, ML);
    k_bgemm<<<NSM, GTHR, GSMEM>>>(AH, AL, W1R, HID,
                                  AH + (size_t)N_SRC * HID, AL + (size_t)N_SRC * HID, W1R, HID,
                                  MH, ML, W1L, HID,
                                  b1, b1,
                                  nullptr, X1H, X1L, HID, 1,
                                  HID / 128, (HID / 128) * 2 * YTILES, 1, 1, 2);

    // BN finalize + apply (+ReLU) -> AH only
    k_bnfinal<<<1, 512>>>(gamma, beta);
    k_bnapply<<<(int)(((size_t)N_TOT * HID / 8 + 255) / 256), 256>>>();

    // layer 2 (1-term, single fp16)
    k_aggregate<<<N_DST, 128>>>(AH, nullptr, MH, nullptr);
    k_bgemm<<<NSM, GTHR, GSMEM>>>(AH, nullptr, W2R, HID,
                                  AH + (size_t)N_SRC * HID, nullptr, W2R, HID,
                                  MH, nullptr, W2L, HID,
                                  b2, b2,
                                  out, nullptr, nullptr, OUTD, 0,
                                  OUTD / 128, (OUTD / 128) * 2 * YTILES, 1, 2, 1);
}